// round 15
// baseline (speedup 1.0000x reference)
#include <cuda_runtime.h>
#include <cuda_fp16.h>
#include <math.h>

// ---------------------------------------------------------------------------
#define NB      2
#define CDIM    768
#define DD      16
#define HH      14
#define WW      14
#define SPAT    (DD*HH*WW)        // 3136
#define NTOKTOT (NB*SPAT)         // 6272
#define NWIN    16
#define NWINB   8
#define NTOK    392
#define NHEADS  24
#define HDIM    32
#define QKVC    (3*CDIM)          // 2304
#define MLPC    (4*CDIM)          // 3072
#define RPBN    2535
#define BIAS_HN (NTOK*NTOK)

// ---------------------------------------------------------------------------
__device__ __align__(128) float  g_xcur[2*NTOKTOT*CDIM];
__device__ __align__(128) __half g_bufA[2*NTOKTOT*CDIM];
__device__ __align__(128) __half g_bufB[2*NTOKTOT*CDIM];
__device__ __align__(128) __half g_qkvh[2*NTOKTOT*QKVC];
__device__ __align__(128) __half g_bigh[2*NTOKTOT*MLPC];
__device__ __align__(128) __half g_bias[4*NHEADS*BIAS_HN];
__device__ __align__(128) float  g_rpbT[4*NHEADS*RPBN];
__device__ __align__(128) float  g_out2[2*NTOKTOT*2];
__device__ __align__(128) int    g_map0[NTOKTOT];
__device__ __align__(128) int    g_map1[NTOKTOT];
__device__ __align__(128) int    g_lab [NWINB*NTOK];
__device__ __align__(128) __half g_wqkv[4*QKVC*CDIM];
__device__ __align__(128) __half g_wproj[4*CDIM*CDIM];
__device__ __align__(128) __half g_wfc1[4*MLPC*CDIM];
__device__ __align__(128) __half g_wfc2[4*CDIM*MLPC];

__device__ __forceinline__ float gelu_f(float x) {
    return 0.5f * x * (1.0f + erff(x * 0.70710678118654752440f));
}

__device__ __forceinline__ unsigned pack_h2(float lo, float hi) {
    unsigned r;
    asm("cvt.rn.f16x2.f32 %0, %1, %2;" : "=r"(r) : "f"(hi), "f"(lo));
    return r;
}

__device__ __forceinline__ void cp16(unsigned saddr, const void* g) {
    asm volatile("cp.async.cg.shared.global [%0], [%1], 16;" :: "r"(saddr), "l"(g) : "memory");
}

__device__ __forceinline__ unsigned smem_u32(const void* p) {
    unsigned a;
    asm("{ .reg .u64 t; cvta.to.shared.u64 t, %1; cvt.u32.u64 %0, t; }" : "=r"(a) : "l"(p));
    return a;
}

#define SW128(off) ((off) ^ (((off) >> 3) & 0x70))

#define LDSM_X4(r0, r1, r2, r3, addr) \
    asm volatile("ldmatrix.sync.aligned.m8n8.x4.shared.b16 {%0,%1,%2,%3}, [%4];" \
                 : "=r"(r0), "=r"(r1), "=r"(r2), "=r"(r3) : "r"(addr))

#define MMA_F16(c, a, b0v, b1v) \
    asm volatile("mma.sync.aligned.m16n8k16.row.col.f32.f16.f16.f32 " \
                 "{%0,%1,%2,%3}, {%4,%5,%6,%7}, {%8,%9}, {%0,%1,%2,%3};" \
                 : "+f"((c)[0]), "+f"((c)[1]), "+f"((c)[2]), "+f"((c)[3]) \
                 : "r"((a)[0]), "r"((a)[1]), "r"((a)[2]), "r"((a)[3]), \
                   "r"(b0v), "r"(b1v))

// ---------------------------------------------------------------------------
__global__ void w2h_kernel(const float* __restrict__ in, __half* __restrict__ out, int n4) {
    int i = blockIdx.x * blockDim.x + threadIdx.x;
    for (; i < n4; i += gridDim.x * blockDim.x) {
        float4 v = ((const float4*)in)[i];
        ((__half2*)out)[2*i]   = __floats2half2_rn(v.x, v.y);
        ((__half2*)out)[2*i+1] = __floats2half2_rn(v.z, v.w);
    }
}

__global__ void build_maps_kernel(int* map0, int* map1, int* lab) {
    int r = blockIdx.x * blockDim.x + threadIdx.x;
    if (r < NTOKTOT) {
        int b = r / SPAT, rem = r % SPAT;
        int wi = rem / NTOK, n = rem % NTOK;
        int bd = wi >> 2, bh = (wi >> 1) & 1, bw = wi & 1;
        int wd = n / 49, wh = (n / 7) % 7, ww = n % 7;
        int d = bd * 8 + wd, h = bh * 7 + wh, w = bw * 7 + ww;
        map0[r] = b * SPAT + d * (HH*WW) + h * WW + w;
        int ds = (d + 4) & 15, hs = (h + 3) % 14, ws = (w + 3) % 14;
        map1[r] = b * SPAT + ds * (HH*WW) + hs * WW + ws;
    }
    if (r < NWINB * NTOK) {
        int wi = r / NTOK, n = r % NTOK;
        int bd = wi >> 2, bh = (wi >> 1) & 1, bw = wi & 1;
        int wd = n / 49, wh = (n / 7) % 7, ww = n % 7;
        int d = bd * 8 + wd, h = bh * 7 + wh, w = bw * 7 + ww;
        int cd = d < 8 ? 0 : (d < 12 ? 1 : 2);
        int ch = h < 7 ? 0 : (h < 11 ? 1 : 2);
        int cw = w < 7 ? 0 : (w < 11 ? 1 : 2);
        lab[r] = cd * 9 + ch * 3 + cw;
    }
}

// (B, C, S) -> (B, S, C), written to BOTH branch residual buffers
__global__ void transpose_dual_kernel(const float* __restrict__ x,
                                      float* __restrict__ out0,
                                      float* __restrict__ out1) {
    __shared__ float tile[32][33];
    int b  = blockIdx.z;
    int s0 = blockIdx.x * 32, c0 = blockIdx.y * 32;
    int tx = threadIdx.x, ty = threadIdx.y;
    #pragma unroll
    for (int i = 0; i < 32; i += 8) {
        int c = c0 + ty + i, s = s0 + tx;
        if (c < CDIM && s < SPAT)
            tile[ty + i][tx] = x[((size_t)b * CDIM + c) * SPAT + s];
    }
    __syncthreads();
    #pragma unroll
    for (int i = 0; i < 32; i += 8) {
        int s = s0 + ty + i, c = c0 + tx;
        if (s < SPAT && c < CDIM) {
            float v = tile[tx][ty + i];
            size_t o = ((size_t)b * SPAT + s) * CDIM + c;
            out0[o] = v;
            out1[o] = v;
        }
    }
}

// rpb [RPBN, NHEADS] -> rpbT [NHEADS, RPBN] for two layers of one branch
__global__ void rpb_transpose_kernel(const float* __restrict__ rpb0,
                                     const float* __restrict__ rpb1,
                                     float* __restrict__ t0,
                                     float* __restrict__ t1) {
    int i = blockIdx.x * blockDim.x + threadIdx.x;
    if (i >= RPBN * NHEADS) return;
    int r = i / NHEADS, h = i % NHEADS;
    t0[h * RPBN + r] = rpb0[i];
    t1[h * RPBN + r] = rpb1[i];
}

// Fused bias gather from transposed tables (L1-resident per-head rows)
__global__ void bias_gather2_kernel(const float* __restrict__ rpbT0,
                                    const float* __restrict__ rpbT1,
                                    const int* __restrict__ rpi,
                                    __half* __restrict__ b0,
                                    __half* __restrict__ b1) {
    int idx = blockIdx.x * blockDim.x + threadIdx.x;
    if (idx >= NHEADS * (BIAS_HN / 2)) return;
    int h  = idx / (BIAS_HN / 2);
    int nm = (idx % (BIAS_HN / 2)) * 2;
    int r0 = rpi[nm], r1 = rpi[nm + 1];
    const float* p0 = rpbT0 + (size_t)h * RPBN;
    const float* p1 = rpbT1 + (size_t)h * RPBN;
    unsigned v0 = pack_h2(p0[r0], p0[r1]);
    unsigned v1 = pack_h2(p1[r0], p1[r1]);
    *(unsigned*)(b0 + (size_t)h * BIAS_HN + nm) = v0;
    *(unsigned*)(b1 + (size_t)h * BIAS_HN + nm) = v1;
}

// ---------------------------------------------------------------------------
// LayerNorm: 4 rows per 256-thread block; 64 threads/row, 12 floats/thread.
// ---------------------------------------------------------------------------
__global__ void __launch_bounds__(256) ln_kernel(const float* __restrict__ in,
                                                 const float* __restrict__ gw,
                                                 const float* __restrict__ gb,
                                                 __half* __restrict__ out,
                                                 const int* __restrict__ map) {
    int rloc = threadIdx.x >> 6;
    int t    = threadIdx.x & 63;
    int r = blockIdx.x * 4 + rloc;
    int src = map ? map[r] : r;
    const float4* xp = (const float4*)(in + (size_t)src * CDIM);
    float4 a = xp[t], b = xp[t + 64], c = xp[t + 128];

    __shared__ float red[4][2];
    __shared__ float stat[4][2];

    float s = (a.x + a.y + a.z + a.w) + (b.x + b.y + b.z + b.w) + (c.x + c.y + c.z + c.w);
    #pragma unroll
    for (int o = 16; o; o >>= 1) s += __shfl_xor_sync(0xffffffffu, s, o);
    if ((t & 31) == 0) red[rloc][t >> 5] = s;
    __syncthreads();
    if (t == 0) stat[rloc][0] = (red[rloc][0] + red[rloc][1]) * (1.0f / CDIM);
    __syncthreads();
    float mu = stat[rloc][0];

    float da[4] = {a.x - mu, a.y - mu, a.z - mu, a.w - mu};
    float db[4] = {b.x - mu, b.y - mu, b.z - mu, b.w - mu};
    float dc[4] = {c.x - mu, c.y - mu, c.z - mu, c.w - mu};
    s = da[0]*da[0] + da[1]*da[1] + da[2]*da[2] + da[3]*da[3]
      + db[0]*db[0] + db[1]*db[1] + db[2]*db[2] + db[3]*db[3]
      + dc[0]*dc[0] + dc[1]*dc[1] + dc[2]*dc[2] + dc[3]*dc[3];
    #pragma unroll
    for (int o = 16; o; o >>= 1) s += __shfl_xor_sync(0xffffffffu, s, o);
    if ((t & 31) == 0) red[rloc][t >> 5] = s;
    __syncthreads();
    if (t == 0) stat[rloc][1] = rsqrtf((red[rloc][0] + red[rloc][1]) * (1.0f / CDIM) + 1e-5f);
    __syncthreads();
    float inv = stat[rloc][1];

    const float4* gwp = (const float4*)gw;
    const float4* gbp = (const float4*)gb;
    __half* o = out + (size_t)r * CDIM;
    #pragma unroll
    for (int seg = 0; seg < 3; seg++) {
        int idx = t + seg * 64;
        float4 g = gwp[idx];
        float4 h = gbp[idx];
        const float* d = seg == 0 ? da : (seg == 1 ? db : dc);
        float v0 = d[0] * inv * g.x + h.x;
        float v1 = d[1] * inv * g.y + h.y;
        float v2 = d[2] * inv * g.z + h.z;
        float v3 = d[3] * inv * g.w + h.w;
        uint2 u;
        u.x = pack_h2(v0, v1);
        u.y = pack_h2(v2, v3);
        *(uint2*)(o + 4 * idx) = u;
    }
}

// ---------------------------------------------------------------------------
// FP16 GEMM: CTA 128x256, BK=64, warp tile 64x64 (2Mx4N), 4-stage cp.async,
// sync->prefetch->wait ordering. SW128 smem, ldmatrix, mma.m16n8k16 fp32 acc.
// ---------------------------------------------------------------------------
#define HASTG 16384
#define HBSTG 32768
#define HGEMM_SMEM (4*HASTG + 4*HBSTG)   // 196608 B

__global__ void __launch_bounds__(256) gemm_h_kernel(
    const __half* __restrict__ A, const __half* __restrict__ W,
    const float* __restrict__ bias, void* __restrict__ Cv,
    int M, int N, int K, int ldC,
    int act_gelu, const int* __restrict__ scatter, int add_resid, int out_half)
{
    extern __shared__ __align__(128) char smg[];
    unsigned sbase = smem_u32(smg);
    unsigned bbase = sbase + 4 * HASTG;
    int tid = threadIdx.x, warp = tid >> 5, lane = tid & 31;
    int wm = warp >> 2, wn = warp & 3;
    int gid = lane >> 2, tig = lane & 3;
    int m0 = blockIdx.y * 128, n0 = blockIdx.x * 256;

    const __half* Ap = A + (size_t)m0 * K;
    const __half* Wp = W + (size_t)n0 * K;
    int NT = K >> 6;

    int ldrow = tid >> 3;
    int ldc   = tid & 7;

    int l7 = lane & 7;
    int a_row = ((lane >> 3) & 1) * 8 + l7;
    int a_cs  = lane >> 4;
    int b_row = ((lane >> 4) & 1) * 8 + l7;
    int b_cs  = (lane >> 3) & 1;

    float acc[4][8][4];
    #pragma unroll
    for (int mi = 0; mi < 4; mi++)
        #pragma unroll
        for (int nj = 0; nj < 8; nj++)
            #pragma unroll
            for (int r = 0; r < 4; r++) acc[mi][nj][r] = 0.0f;

    #pragma unroll
    for (int t = 0; t < 3; t++) {
        #pragma unroll
        for (int l = 0; l < 4; l++) {
            int row = ldrow + l * 32;
            unsigned off = SW128((unsigned)(row * 128 + ldc * 16));
            cp16(sbase + t * HASTG + off, Ap + (size_t)row * K + t * 64 + ldc * 8);
        }
        #pragma unroll
        for (int l = 0; l < 8; l++) {
            int row = ldrow + l * 32;
            unsigned off = SW128((unsigned)(row * 128 + ldc * 16));
            cp16(bbase + t * HBSTG + off, Wp + (size_t)row * K + t * 64 + ldc * 8);
        }
        asm volatile("cp.async.commit_group;" ::: "memory");
    }

    for (int t = 0; t < NT; t++) {
        __syncthreads();
        if (t + 3 < NT) {
            int s2 = (t + 3) & 3;
            #pragma unroll
            for (int l = 0; l < 4; l++) {
                int row = ldrow + l * 32;
                unsigned off = SW128((unsigned)(row * 128 + ldc * 16));
                cp16(sbase + s2 * HASTG + off, Ap + (size_t)row * K + (t+3) * 64 + ldc * 8);
            }
            #pragma unroll
            for (int l = 0; l < 8; l++) {
                int row = ldrow + l * 32;
                unsigned off = SW128((unsigned)(row * 128 + ldc * 16));
                cp16(bbase + s2 * HBSTG + off, Wp + (size_t)row * K + (t+3) * 64 + ldc * 8);
            }
            asm volatile("cp.async.commit_group;" ::: "memory");
            asm volatile("cp.async.wait_group 3;" ::: "memory");
        } else if (t + 3 == NT) {
            asm volatile("cp.async.wait_group 2;" ::: "memory");
        } else if (t + 2 == NT) {
            asm volatile("cp.async.wait_group 1;" ::: "memory");
        } else {
            asm volatile("cp.async.wait_group 0;" ::: "memory");
        }
        __syncthreads();
        unsigned sA = sbase + (t & 3) * HASTG;
        unsigned sB = bbase + (t & 3) * HBSTG;

        #pragma unroll
        for (int s = 0; s < 4; s++) {
            unsigned af[4][4], bf[8][2];
            #pragma unroll
            for (int mi = 0; mi < 4; mi++) {
                int row = wm * 64 + mi * 16 + a_row;
                int ch  = 2 * s + a_cs;
                unsigned ad = sA + SW128((unsigned)(row * 128 + ch * 16));
                LDSM_X4(af[mi][0], af[mi][1], af[mi][2], af[mi][3], ad);
            }
            #pragma unroll
            for (int np = 0; np < 4; np++) {
                int row = wn * 64 + np * 16 + b_row;
                int ch  = 2 * s + b_cs;
                unsigned bd = sB + SW128((unsigned)(row * 128 + ch * 16));
                LDSM_X4(bf[2*np][0], bf[2*np][1], bf[2*np+1][0], bf[2*np+1][1], bd);
            }
            #pragma unroll
            for (int mi = 0; mi < 4; mi++)
                #pragma unroll
                for (int nj = 0; nj < 8; nj++)
                    MMA_F16(acc[mi][nj], af[mi], bf[nj][0], bf[nj][1]);
        }
    }

    float bs0[8], bs1[8];
    #pragma unroll
    for (int nj = 0; nj < 8; nj++) {
        int col = n0 + wn * 64 + nj * 8 + 2 * tig;
        bs0[nj] = bias[col];
        bs1[nj] = bias[col + 1];
    }
    #pragma unroll
    for (int mi = 0; mi < 4; mi++) {
        #pragma unroll
        for (int half = 0; half < 2; half++) {
            int gr = m0 + wm * 64 + mi * 16 + gid + half * 8;
            int tr = scatter ? scatter[gr] : gr;
            #pragma unroll
            for (int nj = 0; nj < 8; nj++) {
                int col = n0 + wn * 64 + nj * 8 + 2 * tig;
                float v0 = acc[mi][nj][half * 2 + 0] + bs0[nj];
                float v1 = acc[mi][nj][half * 2 + 1] + bs1[nj];
                if (act_gelu) { v0 = gelu_f(v0); v1 = gelu_f(v1); }
                if (out_half) {
                    unsigned* hp = (unsigned*)((__half*)Cv + (size_t)tr * ldC + col);
                    *hp = pack_h2(v0, v1);
                } else {
                    float* cp = (float*)Cv + (size_t)tr * ldC + col;
                    if (add_resid) { v0 += cp[0]; v1 += cp[1]; }
                    cp[0] = v0; cp[1] = v1;
                }
            }
        }
    }
}

// ---------------------------------------------------------------------------
// Tensor-core window attention, fp16 bias table. 2 CTAs/SM target.
// ---------------------------------------------------------------------------
#define QS_STRIDE 40
#define VT_STRIDE 408
#define ATTN_SMEM_B (400*QS_STRIDE*2*2 + 32*VT_STRIDE*2 + 400*4)

__global__ void __launch_bounds__(256, 2) attn_mma_kernel(
    const __half* __restrict__ qkv,
    const __half* __restrict__ biasT,
    const int* __restrict__ labels,
    __half* __restrict__ out, int shifted)
{
    extern __shared__ __align__(16) char smA[];
    __half* Qs = (__half*)smA;
    __half* Ks = Qs + 400 * QS_STRIDE;
    __half* Vt = Ks + 400 * QS_STRIDE;
    int* lab = (int*)(Vt + 32 * VT_STRIDE);
    int h = blockIdx.x, w = blockIdx.y;
    int tid = threadIdx.x;
    int rbase = w * NTOK;

    const __half hz = __float2half(0.0f);
    for (int i = tid; i < 8 * QS_STRIDE; i += 256) {
        Qs[392 * QS_STRIDE + i] = hz;
        Ks[392 * QS_STRIDE + i] = hz;
    }
    for (int i = tid; i < 32 * 8; i += 256) {
        int d = i >> 3, c = i & 7;
        Vt[d * VT_STRIDE + 392 + c] = hz;
    }

    for (int i = tid; i < 392 * 4; i += 256) {
        int m = i >> 2, c = i & 3;
        const __half* base = qkv + (size_t)(rbase + m) * QKVC + h * HDIM + c * 8;
        *(uint4*)(Qs + m * QS_STRIDE + c * 8) = *(const uint4*)(base);
        *(uint4*)(Ks + m * QS_STRIDE + c * 8) = *(const uint4*)(base + CDIM);
    }
    for (int m = tid; m < 392; m += 256) {
        const uint4* vp = (const uint4*)(qkv + (size_t)(rbase + m) * QKVC + 2 * CDIM + h * HDIM);
        __half vv[32];
        #pragma unroll
        for (int q = 0; q < 4; q++) ((uint4*)vv)[q] = vp[q];
        #pragma unroll
        for (int d = 0; d < 32; d++) Vt[d * VT_STRIDE + m] = vv[d];
    }
    for (int i = tid; i < 400; i += 256)
        lab[i] = (shifted && i < NTOK) ? labels[(w & 7) * NTOK + i] : 0;
    __syncthreads();

    int warp = tid >> 5, lane = tid & 31;
    int gid = lane >> 2, tig = lane & 3;
    int l7 = lane & 7;
    int a_row = ((lane >> 3) & 1) * 8 + l7;
    int a_cs  = lane >> 4;
    int b_row = ((lane >> 4) & 1) * 8 + l7;
    int b_cs  = (lane >> 3) & 1;
    const float scale = 0.17677669529663689f;

    unsigned qsb = smem_u32(Qs);
    unsigned ksb = smem_u32(Ks);
    unsigned vtb = smem_u32(Vt);

    for (int mt = warp; mt < 25; mt += 8) {
        unsigned aq[2][4];
        #pragma unroll
        for (int s = 0; s < 2; s++) {
            unsigned ad = qsb + (unsigned)(((mt * 16 + a_row) * QS_STRIDE + (2*s + a_cs) * 8) * 2);
            LDSM_X4(aq[s][0], aq[s][1], aq[s][2], aq[s][3], ad);
        }
        int q0 = mt * 16 + gid, q1 = q0 + 8;
        int q1ok = (mt != 24);
        int labq0 = lab[q0], labq1 = lab[q1];
        const __half* bp0 = biasT + ((size_t)h * NTOK + q0) * NTOK;
        const __half* bp1 = q1ok ? biasT + ((size_t)h * NTOK + q1) * NTOK : biasT;

        float mr0 = -1e30f, mr1 = -1e30f, lr0 = 0.f, lr1 = 0.f;
        float acc[4][4];
        #pragma unroll
        for (int j = 0; j < 4; j++)
            #pragma unroll
            for (int r = 0; r < 4; r++) acc[j][r] = 0.f;

        for (int nt = 0; nt < 25; nt++) {
            float c0[4] = {0.f, 0.f, 0.f, 0.f};
            float c1[4] = {0.f, 0.f, 0.f, 0.f};
            #pragma unroll
            for (int s = 0; s < 2; s++) {
                unsigned bd = ksb + (unsigned)(((nt * 16 + b_row) * QS_STRIDE + (2*s + b_cs) * 8) * 2);
                unsigned bf0, bf1, bf2, bf3;
                LDSM_X4(bf0, bf1, bf2, bf3, bd);
                MMA_F16(c0, aq[s], bf0, bf1);
                MMA_F16(c1, aq[s], bf2, bf3);
            }
            float sv[2][4];
            #pragma unroll
            for (int f = 0; f < 2; f++) {
                float* c = f ? c1 : c0;
                int k0 = nt * 16 + f * 8 + 2 * tig;
                int kvalid = !(nt == 24 && f == 1);
                if (kvalid) {
                    __half2 hb0 = *(const __half2*)(bp0 + k0);
                    float b00 = __low2float(hb0), b01 = __high2float(hb0);
                    float b10 = 0.f, b11 = 0.f;
                    if (q1ok) {
                        __half2 hb1 = *(const __half2*)(bp1 + k0);
                        b10 = __low2float(hb1); b11 = __high2float(hb1);
                    }
                    float mk0 = 0.f, mk1 = 0.f;
                    if (shifted) {
                        int lk0 = lab[k0], lk1 = lab[k0 + 1];
                        mk0 = (lk0 != labq0) ? -100.f : 0.f;
                        mk1 = (lk1 != labq0) ? -100.f : 0.f;
                        b10 += (lk0 != labq1) ? -100.f : 0.f;
                        b11 += (lk1 != labq1) ? -100.f : 0.f;
                    }
                    sv[f][0] = c[0] * scale + b00 + mk0;
                    sv[f][1] = c[1] * scale + b01 + mk1;
                    sv[f][2] = c[2] * scale + b10;
                    sv[f][3] = c[3] * scale + b11;
                } else {
                    sv[f][0] = sv[f][1] = sv[f][2] = sv[f][3] = -1e30f;
                }
            }
            float tm0 = fmaxf(fmaxf(sv[0][0], sv[0][1]), fmaxf(sv[1][0], sv[1][1]));
            float tm1 = fmaxf(fmaxf(sv[0][2], sv[0][3]), fmaxf(sv[1][2], sv[1][3]));
            tm0 = fmaxf(tm0, __shfl_xor_sync(0xffffffffu, tm0, 1));
            tm0 = fmaxf(tm0, __shfl_xor_sync(0xffffffffu, tm0, 2));
            tm1 = fmaxf(tm1, __shfl_xor_sync(0xffffffffu, tm1, 1));
            tm1 = fmaxf(tm1, __shfl_xor_sync(0xffffffffu, tm1, 2));
            float mn0 = fmaxf(mr0, tm0), mn1 = fmaxf(mr1, tm1);
            float al0 = __expf(mr0 - mn0), al1 = __expf(mr1 - mn1);
            float e[2][4];
            #pragma unroll
            for (int f = 0; f < 2; f++) {
                e[f][0] = __expf(sv[f][0] - mn0);
                e[f][1] = __expf(sv[f][1] - mn0);
                e[f][2] = __expf(sv[f][2] - mn1);
                e[f][3] = __expf(sv[f][3] - mn1);
            }
            float ts0 = e[0][0] + e[0][1] + e[1][0] + e[1][1];
            float ts1 = e[0][2] + e[0][3] + e[1][2] + e[1][3];
            ts0 += __shfl_xor_sync(0xffffffffu, ts0, 1);
            ts0 += __shfl_xor_sync(0xffffffffu, ts0, 2);
            ts1 += __shfl_xor_sync(0xffffffffu, ts1, 1);
            ts1 += __shfl_xor_sync(0xffffffffu, ts1, 2);
            lr0 = lr0 * al0 + ts0;
            lr1 = lr1 * al1 + ts1;
            mr0 = mn0; mr1 = mn1;
            #pragma unroll
            for (int j = 0; j < 4; j++) {
                acc[j][0] *= al0; acc[j][1] *= al0;
                acc[j][2] *= al1; acc[j][3] *= al1;
            }
            unsigned pa[4];
            pa[0] = pack_h2(e[0][0], e[0][1]);
            pa[1] = pack_h2(e[0][2], e[0][3]);
            pa[2] = pack_h2(e[1][0], e[1][1]);
            pa[3] = pack_h2(e[1][2], e[1][3]);
            #pragma unroll
            for (int g = 0; g < 2; g++) {
                unsigned bd = vtb + (unsigned)(((g * 16 + b_row) * VT_STRIDE + nt * 16 + b_cs * 8) * 2);
                unsigned bf0, bf1, bf2, bf3;
                LDSM_X4(bf0, bf1, bf2, bf3, bd);
                MMA_F16(acc[2*g],   pa, bf0, bf1);
                MMA_F16(acc[2*g+1], pa, bf2, bf3);
            }
        }
        float li0 = 1.0f / lr0, li1 = 1.0f / lr1;
        if (q0 < NTOK) {
            __half* op = out + (size_t)(rbase + q0) * CDIM + h * HDIM;
            #pragma unroll
            for (int j = 0; j < 4; j++)
                *(unsigned*)(op + j * 8 + 2 * tig) = pack_h2(acc[j][0] * li0, acc[j][1] * li0);
        }
        if (q1ok) {
            __half* op = out + (size_t)(rbase + q1) * CDIM + h * HDIM;
            #pragma unroll
            for (int j = 0; j < 4; j++)
                *(unsigned*)(op + j * 8 + 2 * tig) = pack_h2(acc[j][2] * li1, acc[j][3] * li1);
        }
    }
}

// ---------------------------------------------------------------------------
// Fused head: c1 (768->64 GEMM + GELU) and c2 (64->2 dot + GELU) in one kernel.
// CTA = 64 tokens; after the k-loop the full 64x64 gelu(c1) tile is staged in
// smem and 128 threads compute the two c2 outputs per token (same serial
// k-order as the old c2_kernel -> bit-identical results).
// ---------------------------------------------------------------------------
#define GBM2 64
#define GBK 16
#define A2_STRIDE 68
#define B_STRIDE 68

__global__ void __launch_bounds__(256) head_kernel(
    const __half* __restrict__ A, const float* __restrict__ W,
    const float* __restrict__ bias,
    const float* __restrict__ w2, const float* __restrict__ b2,
    float* __restrict__ out2)
{
    __shared__ float As[GBK * A2_STRIDE];
    __shared__ float Bs[GBK * B_STRIDE];
    __shared__ float Cs[GBM2 * A2_STRIDE];
    __shared__ float w2s[2][64];
    __shared__ float b2s[2];
    int tid = threadIdx.x;
    int tx = tid & 15, ty = tid >> 4;
    int m0 = blockIdx.y * GBM2;
    const __half* Aptr = A + (size_t)m0 * CDIM;
    float acc[4][4];
    #pragma unroll
    for (int i = 0; i < 4; i++)
        #pragma unroll
        for (int j = 0; j < 4; j++) acc[i][j] = 0.0f;

    if (tid < 128) w2s[tid >> 6][tid & 63] = w2[tid];
    if (tid < 2)   b2s[tid] = b2[tid];

    int ldrow = tid >> 2;
    int ldkc  = (tid & 3) * 4;

    for (int k0 = 0; k0 < CDIM; k0 += GBK) {
        {
            const __half* ap = Aptr + (size_t)ldrow * CDIM + k0 + ldkc;
            __half2 h0 = *(const __half2*)(ap);
            __half2 h1 = *(const __half2*)(ap + 2);
            As[(ldkc + 0) * A2_STRIDE + ldrow] = __low2float(h0);
            As[(ldkc + 1) * A2_STRIDE + ldrow] = __high2float(h0);
            As[(ldkc + 2) * A2_STRIDE + ldrow] = __low2float(h1);
            As[(ldkc + 3) * A2_STRIDE + ldrow] = __high2float(h1);
        }
        {
            float4 v = *(const float4*)(W + (size_t)ldrow * CDIM + k0 + ldkc);
            Bs[(ldkc + 0) * B_STRIDE + ldrow] = v.x;
            Bs[(ldkc + 1) * B_STRIDE + ldrow] = v.y;
            Bs[(ldkc + 2) * B_STRIDE + ldrow] = v.z;
            Bs[(ldkc + 3) * B_STRIDE + ldrow] = v.w;
        }
        __syncthreads();
        #pragma unroll
        for (int kk = 0; kk < GBK; kk++) {
            float4 a4 = *(const float4*)&As[kk * A2_STRIDE + ty * 4];
            float4 b4 = *(const float4*)&Bs[kk * B_STRIDE + tx * 4];
            float a[4] = {a4.x, a4.y, a4.z, a4.w};
            float b[4] = {b4.x, b4.y, b4.z, b4.w};
            #pragma unroll
            for (int i = 0; i < 4; i++)
                #pragma unroll
                for (int j = 0; j < 4; j++)
                    acc[i][j] += a[i] * b[j];
        }
        __syncthreads();
    }
    // stage gelu(c1) into smem: Cs[token][col]
    #pragma unroll
    for (int i = 0; i < 4; i++) {
        int row = ty * 4 + i;
        #pragma unroll
        for (int j = 0; j < 4; j++) {
            int col = tx * 4 + j;
            Cs[row * A2_STRIDE + col] = gelu_f(acc[i][j] + bias[col]);
        }
    }
    __syncthreads();
    // c2: 128 threads, each one (token, p) pair, serial k-order (bit-identical)
    if (tid < 128) {
        int t = tid >> 1, p = tid & 1;
        const float* row = &Cs[t * A2_STRIDE];
        const float* wp = w2s[p];
        float s = b2s[p];
        #pragma unroll
        for (int k = 0; k < 64; k++) s += row[k] * wp[k];
        out2[(size_t)(m0 + t) * 2 + p] = gelu_f(s);
    }
}

__global__ void final_mul_kernel(const float* __restrict__ o2, float* __restrict__ out) {
    int i = blockIdx.x * blockDim.x + threadIdx.x;
    if (i >= NB * 2 * SPAT) return;
    int b = i / (2 * SPAT);
    int rem = i % (2 * SPAT);
    int p = rem / SPAT;
    int sp = rem % SPAT;
    int t = b * SPAT + sp;
    out[i] = o2[t * 2 + p] * o2[2 * NTOKTOT + t * 2 + p];
}

// ---------------------------------------------------------------------------
extern "C" void kernel_launch(void* const* d_in, const int* in_sizes, int n_in,
                              void* d_out, int out_size) {
    (void)in_sizes; (void)n_in; (void)out_size;
    const float* x      = (const float*)d_in[0];
    const float* n1_g   = (const float*)d_in[1];
    const float* n1_b   = (const float*)d_in[2];
    const float* qkv_w  = (const float*)d_in[3];
    const float* qkv_b  = (const float*)d_in[4];
    const float* proj_w = (const float*)d_in[5];
    const float* proj_b = (const float*)d_in[6];
    const float* rpb    = (const float*)d_in[7];
    const float* n2_g   = (const float*)d_in[8];
    const float* n2_b   = (const float*)d_in[9];
    const float* fc1_w  = (const float*)d_in[10];
    const float* fc1_b  = (const float*)d_in[11];
    const float* fc2_w  = (const float*)d_in[12];
    const float* fc2_b  = (const float*)d_in[13];
    const float* hln_g  = (const float*)d_in[14];
    const float* hln_b  = (const float*)d_in[15];
    const float* c1_w   = (const float*)d_in[16];
    const float* c1_b   = (const float*)d_in[17];
    const float* c2_w   = (const float*)d_in[18];
    const float* c2_b   = (const float*)d_in[19];
    const int*   rpi    = (const int*)d_in[20];
    float* out = (float*)d_out;

    float *xcur0, *out2, *rpbT0;
    __half *bufA0, *bufB0, *qkvh0, *bigh0, *bias0;
    __half *wqkv, *wproj, *wfc1, *wfc2;
    int *map0, *map1, *lab;
    cudaGetSymbolAddress((void**)&xcur0,   g_xcur);
    cudaGetSymbolAddress((void**)&bufA0,   g_bufA);
    cudaGetSymbolAddress((void**)&bufB0,   g_bufB);
    cudaGetSymbolAddress((void**)&qkvh0,   g_qkvh);
    cudaGetSymbolAddress((void**)&bigh0,   g_bigh);
    cudaGetSymbolAddress((void**)&bias0,   g_bias);
    cudaGetSymbolAddress((void**)&rpbT0,   g_rpbT);
    cudaGetSymbolAddress((void**)&out2,    g_out2);
    cudaGetSymbolAddress((void**)&map0,    g_map0);
    cudaGetSymbolAddress((void**)&map1,    g_map1);
    cudaGetSymbolAddress((void**)&lab,     g_lab);
    cudaGetSymbolAddress((void**)&wqkv,    g_wqkv);
    cudaGetSymbolAddress((void**)&wproj,   g_wproj);
    cudaGetSymbolAddress((void**)&wfc1,    g_wfc1);
    cudaGetSymbolAddress((void**)&wfc2,    g_wfc2);

    cudaFuncSetAttribute(attn_mma_kernel, cudaFuncAttributeMaxDynamicSharedMemorySize, ATTN_SMEM_B);
    cudaFuncSetAttribute(gemm_h_kernel, cudaFuncAttributeMaxDynamicSharedMemorySize, HGEMM_SMEM);

    static cudaStream_t s_br1 = nullptr, s_aux[2] = {nullptr, nullptr};
    static cudaEvent_t ev_fork = nullptr, ev_join = nullptr, ev_maps = nullptr, ev_tr = nullptr;
    static cudaEvent_t evA[2], evB[2], evC[2];
    if (s_br1 == nullptr) {
        cudaStreamCreateWithFlags(&s_br1, cudaStreamNonBlocking);
        cudaStreamCreateWithFlags(&s_aux[0], cudaStreamNonBlocking);
        cudaStreamCreateWithFlags(&s_aux[1], cudaStreamNonBlocking);
        cudaEventCreateWithFlags(&ev_fork, cudaEventDisableTiming);
        cudaEventCreateWithFlags(&ev_join, cudaEventDisableTiming);
        cudaEventCreateWithFlags(&ev_maps, cudaEventDisableTiming);
        cudaEventCreateWithFlags(&ev_tr,   cudaEventDisableTiming);
        for (int b = 0; b < 2; b++) {
            cudaEventCreateWithFlags(&evA[b], cudaEventDisableTiming);
            cudaEventCreateWithFlags(&evB[b], cudaEventDisableTiming);
            cudaEventCreateWithFlags(&evC[b], cudaEventDisableTiming);
        }
    }

    cudaEventRecord(ev_fork, 0);
    cudaStreamWaitEvent(s_br1, ev_fork, 0);
    cudaStreamWaitEvent(s_aux[0], ev_fork, 0);
    cudaStreamWaitEvent(s_aux[1], ev_fork, 0);

    build_maps_kernel<<<(NTOKTOT + 255) / 256, 256, 0, s_aux[0]>>>(map0, map1, lab);
    cudaEventRecord(ev_maps, s_aux[0]);
    {
        dim3 blk(32, 8), grd(SPAT / 32, CDIM / 32, NB);
        transpose_dual_kernel<<<grd, blk, 0, 0>>>(x, xcur0, xcur0 + (size_t)NTOKTOT * CDIM);
    }
    cudaEventRecord(ev_tr, 0);
    cudaStreamWaitEvent(0, ev_maps, 0);
    cudaStreamWaitEvent(s_br1, ev_maps, 0);
    cudaStreamWaitEvent(s_br1, ev_tr, 0);

    for (int br = 0; br < 2; br++) {
        cudaStream_t ax = s_aux[br];
        int ib0 = br * 2, ib1 = br * 2 + 1;
        w2h_kernel<<<512, 256, 0, ax>>>(qkv_w + (size_t)br * 2 * QKVC * CDIM,
                                        wqkv + (size_t)br * 2 * QKVC * CDIM, 2 * QKVC * CDIM / 4);
        cudaEventRecord(evA[br], ax);
        rpb_transpose_kernel<<<(RPBN * NHEADS + 255) / 256, 256, 0, ax>>>(
            rpb + (size_t)ib0 * RPBN * NHEADS, rpb + (size_t)ib1 * RPBN * NHEADS,
            rpbT0 + (size_t)ib0 * NHEADS * RPBN, rpbT0 + (size_t)ib1 * NHEADS * RPBN);
        bias_gather2_kernel<<<(NHEADS * (BIAS_HN / 2) + 255) / 256, 256, 0, ax>>>(
            rpbT0 + (size_t)ib0 * NHEADS * RPBN, rpbT0 + (size_t)ib1 * NHEADS * RPBN, rpi,
            bias0 + (size_t)ib0 * NHEADS * BIAS_HN, bias0 + (size_t)ib1 * NHEADS * BIAS_HN);
        cudaEventRecord(evB[br], ax);
        w2h_kernel<<<512, 256, 0, ax>>>(proj_w + (size_t)br * 2 * CDIM * CDIM,
                                        wproj + (size_t)br * 2 * CDIM * CDIM, 2 * CDIM * CDIM / 4);
        w2h_kernel<<<512, 256, 0, ax>>>(fc1_w + (size_t)br * 2 * MLPC * CDIM,
                                        wfc1 + (size_t)br * 2 * MLPC * CDIM, 2 * MLPC * CDIM / 4);
        w2h_kernel<<<512, 256, 0, ax>>>(fc2_w + (size_t)br * 2 * CDIM * MLPC,
                                        wfc2 + (size_t)br * 2 * CDIM * MLPC, 2 * CDIM * MLPC / 4);
        cudaEventRecord(evC[br], ax);
    }

    auto gemm = [&](cudaStream_t st, const __half* A, const __half* W, const float* bias,
                    void* C, int M, int N, int K, int ldC, int gelu, const int* scat,
                    int resid, int out_half) {
        dim3 grid(N / 256, M / 128);
        gemm_h_kernel<<<grid, 256, HGEMM_SMEM, st>>>(A, W, bias, C, M, N, K, ldC,
                                                     gelu, scat, resid, out_half);
    };

    for (int br = 0; br < 2; br++) {
        cudaStream_t st = br ? s_br1 : (cudaStream_t)0;
        float*  xcur  = xcur0  + (size_t)br * NTOKTOT * CDIM;
        __half* bufA  = bufA0  + (size_t)br * NTOKTOT * CDIM;
        __half* bufB  = bufB0  + (size_t)br * NTOKTOT * CDIM;
        __half* qkvh  = qkvh0  + (size_t)br * NTOKTOT * QKVC;
        __half* bigh  = bigh0  + (size_t)br * NTOKTOT * MLPC;

        for (int bl = 0; bl < 2; bl++) {
            int ib = br * 2 + bl;
            int shifted = bl;
            const int* map = shifted ? map1 : map0;
            __half* biasb = bias0 + (size_t)ib * NHEADS * BIAS_HN;

            ln_kernel<<<NTOKTOT / 4, 256, 0, st>>>(xcur, n1_g + ib * CDIM, n1_b + ib * CDIM, bufA, map);

            if (bl == 0) cudaStreamWaitEvent(st, evA[br], 0);
            gemm(st, bufA, wqkv + (size_t)ib * QKVC * CDIM, qkv_b + ib * QKVC,
                 qkvh, NTOKTOT, QKVC, CDIM, QKVC, 0, nullptr, 0, 1);

            if (bl == 0) cudaStreamWaitEvent(st, evB[br], 0);
            {
                dim3 grd(NHEADS, NWIN);
                attn_mma_kernel<<<grd, 256, ATTN_SMEM_B, st>>>(qkvh, biasb, lab, bufB, shifted);
            }

            if (bl == 0) cudaStreamWaitEvent(st, evC[br], 0);
            gemm(st, bufB, wproj + (size_t)ib * CDIM * CDIM, proj_b + ib * CDIM,
                 xcur, NTOKTOT, CDIM, CDIM, CDIM, 0, map, 1, 0);

            ln_kernel<<<NTOKTOT / 4, 256, 0, st>>>(xcur, n2_g + ib * CDIM, n2_b + ib * CDIM, bufA, nullptr);

            gemm(st, bufA, wfc1 + (size_t)ib * MLPC * CDIM, fc1_b + ib * MLPC,
                 bigh, NTOKTOT, MLPC, CDIM, MLPC, 1, nullptr, 0, 1);

            gemm(st, bigh, wfc2 + (size_t)ib * CDIM * MLPC, fc2_b + ib * CDIM,
                 xcur, NTOKTOT, CDIM, MLPC, CDIM, 0, nullptr, 1, 0);
        }
        ln_kernel<<<NTOKTOT / 4, 256, 0, st>>>(xcur, hln_g + br * CDIM, hln_b + br * CDIM, bufA, nullptr);
        {
            dim3 grid(1, NTOKTOT / GBM2);
            head_kernel<<<grid, 256, 0, st>>>(bufA, c1_w + (size_t)br * 64 * CDIM,
                                              c1_b + br * 64, c2_w + br * 2 * 64,
                                              c2_b + br * 2, out2 + (size_t)br * NTOKTOT * 2);
        }
    }

    cudaEventRecord(ev_join, s_br1);
    cudaStreamWaitEvent((cudaStream_t)0, ev_join, 0);
    final_mul_kernel<<<(NB * 2 * SPAT + 255) / 256, 256, 0, 0>>>(out2, out);
}

// round 16
// speedup vs baseline: 1.0055x; 1.0055x over previous
#include <cuda_runtime.h>
#include <cuda_fp16.h>
#include <math.h>

// ---------------------------------------------------------------------------
#define NB      2
#define CDIM    768
#define DD      16
#define HH      14
#define WW      14
#define SPAT    (DD*HH*WW)        // 3136
#define NTOKTOT (NB*SPAT)         // 6272
#define NWIN    16
#define NWINB   8
#define NTOK    392
#define NHEADS  24
#define HDIM    32
#define QKVC    (3*CDIM)          // 2304
#define MLPC    (4*CDIM)          // 3072
#define RPBN    2535
#define BIAS_HN (NTOK*NTOK)

// ---------------------------------------------------------------------------
__device__ __align__(128) float  g_xcur[2*NTOKTOT*CDIM];
__device__ __align__(128) __half g_bufA[2*NTOKTOT*CDIM];
__device__ __align__(128) __half g_bufB[2*NTOKTOT*CDIM];
__device__ __align__(128) __half g_qkvh[2*NTOKTOT*QKVC];
__device__ __align__(128) __half g_bigh[2*NTOKTOT*MLPC];
__device__ __align__(128) __half g_bias[4*NHEADS*BIAS_HN];
__device__ __align__(128) float  g_rpbT[4*NHEADS*RPBN];
__device__ __align__(128) float  g_out2[2*NTOKTOT*2];
__device__ __align__(128) int    g_map0[NTOKTOT];
__device__ __align__(128) int    g_map1[NTOKTOT];
__device__ __align__(128) int    g_lab [NWINB*NTOK];
__device__ __align__(128) __half g_wqkv[4*QKVC*CDIM];
__device__ __align__(128) __half g_wproj[4*CDIM*CDIM];
__device__ __align__(128) __half g_wfc1[4*MLPC*CDIM];
__device__ __align__(128) __half g_wfc2[4*CDIM*MLPC];

__device__ __forceinline__ float gelu_f(float x) {
    return 0.5f * x * (1.0f + erff(x * 0.70710678118654752440f));
}

__device__ __forceinline__ unsigned pack_h2(float lo, float hi) {
    unsigned r;
    asm("cvt.rn.f16x2.f32 %0, %1, %2;" : "=r"(r) : "f"(hi), "f"(lo));
    return r;
}

__device__ __forceinline__ void cp16(unsigned saddr, const void* g) {
    asm volatile("cp.async.cg.shared.global [%0], [%1], 16;" :: "r"(saddr), "l"(g) : "memory");
}

__device__ __forceinline__ unsigned smem_u32(const void* p) {
    unsigned a;
    asm("{ .reg .u64 t; cvta.to.shared.u64 t, %1; cvt.u32.u64 %0, t; }" : "=r"(a) : "l"(p));
    return a;
}

#define SW128(off) ((off) ^ (((off) >> 3) & 0x70))

#define LDSM_X4(r0, r1, r2, r3, addr) \
    asm volatile("ldmatrix.sync.aligned.m8n8.x4.shared.b16 {%0,%1,%2,%3}, [%4];" \
                 : "=r"(r0), "=r"(r1), "=r"(r2), "=r"(r3) : "r"(addr))

#define MMA_F16(c, a, b0v, b1v) \
    asm volatile("mma.sync.aligned.m16n8k16.row.col.f32.f16.f16.f32 " \
                 "{%0,%1,%2,%3}, {%4,%5,%6,%7}, {%8,%9}, {%0,%1,%2,%3};" \
                 : "+f"((c)[0]), "+f"((c)[1]), "+f"((c)[2]), "+f"((c)[3]) \
                 : "r"((a)[0]), "r"((a)[1]), "r"((a)[2]), "r"((a)[3]), \
                   "r"(b0v), "r"(b1v))

// ---------------------------------------------------------------------------
__global__ void w2h_kernel(const float* __restrict__ in, __half* __restrict__ out, int n4) {
    int i = blockIdx.x * blockDim.x + threadIdx.x;
    for (; i < n4; i += gridDim.x * blockDim.x) {
        float4 v = ((const float4*)in)[i];
        ((__half2*)out)[2*i]   = __floats2half2_rn(v.x, v.y);
        ((__half2*)out)[2*i+1] = __floats2half2_rn(v.z, v.w);
    }
}

// Convert three weight blobs in one launch (grid-stride over concatenation)
__global__ void w2h3_kernel(const float* __restrict__ s0, __half* __restrict__ d0, int n0,
                            const float* __restrict__ s1, __half* __restrict__ d1, int n1,
                            const float* __restrict__ s2, __half* __restrict__ d2, int n2) {
    int total = n0 + n1 + n2;
    for (int i = blockIdx.x * blockDim.x + threadIdx.x; i < total;
         i += gridDim.x * blockDim.x) {
        const float* s; __half* d; int j;
        if (i < n0)           { s = s0; d = d0; j = i; }
        else if (i < n0 + n1) { s = s1; d = d1; j = i - n0; }
        else                  { s = s2; d = d2; j = i - n0 - n1; }
        float4 v = ((const float4*)s)[j];
        ((__half2*)d)[2*j]   = __floats2half2_rn(v.x, v.y);
        ((__half2*)d)[2*j+1] = __floats2half2_rn(v.z, v.w);
    }
}

__global__ void build_maps_kernel(int* map0, int* map1, int* lab) {
    int r = blockIdx.x * blockDim.x + threadIdx.x;
    if (r < NTOKTOT) {
        int b = r / SPAT, rem = r % SPAT;
        int wi = rem / NTOK, n = rem % NTOK;
        int bd = wi >> 2, bh = (wi >> 1) & 1, bw = wi & 1;
        int wd = n / 49, wh = (n / 7) % 7, ww = n % 7;
        int d = bd * 8 + wd, h = bh * 7 + wh, w = bw * 7 + ww;
        map0[r] = b * SPAT + d * (HH*WW) + h * WW + w;
        int ds = (d + 4) & 15, hs = (h + 3) % 14, ws = (w + 3) % 14;
        map1[r] = b * SPAT + ds * (HH*WW) + hs * WW + ws;
    }
    if (r < NWINB * NTOK) {
        int wi = r / NTOK, n = r % NTOK;
        int bd = wi >> 2, bh = (wi >> 1) & 1, bw = wi & 1;
        int wd = n / 49, wh = (n / 7) % 7, ww = n % 7;
        int d = bd * 8 + wd, h = bh * 7 + wh, w = bw * 7 + ww;
        int cd = d < 8 ? 0 : (d < 12 ? 1 : 2);
        int ch = h < 7 ? 0 : (h < 11 ? 1 : 2);
        int cw = w < 7 ? 0 : (w < 11 ? 1 : 2);
        lab[r] = cd * 9 + ch * 3 + cw;
    }
}

// (B, C, S) -> (B, S, C), written to BOTH branch residual buffers
__global__ void transpose_dual_kernel(const float* __restrict__ x,
                                      float* __restrict__ out0,
                                      float* __restrict__ out1) {
    __shared__ float tile[32][33];
    int b  = blockIdx.z;
    int s0 = blockIdx.x * 32, c0 = blockIdx.y * 32;
    int tx = threadIdx.x, ty = threadIdx.y;
    #pragma unroll
    for (int i = 0; i < 32; i += 8) {
        int c = c0 + ty + i, s = s0 + tx;
        if (c < CDIM && s < SPAT)
            tile[ty + i][tx] = x[((size_t)b * CDIM + c) * SPAT + s];
    }
    __syncthreads();
    #pragma unroll
    for (int i = 0; i < 32; i += 8) {
        int s = s0 + ty + i, c = c0 + tx;
        if (s < SPAT && c < CDIM) {
            float v = tile[tx][ty + i];
            size_t o = ((size_t)b * SPAT + s) * CDIM + c;
            out0[o] = v;
            out1[o] = v;
        }
    }
}

// rpb [RPBN, NHEADS] -> rpbT [NHEADS, RPBN] for two layers of one branch
__global__ void rpb_transpose_kernel(const float* __restrict__ rpb0,
                                     const float* __restrict__ rpb1,
                                     float* __restrict__ t0,
                                     float* __restrict__ t1) {
    int i = blockIdx.x * blockDim.x + threadIdx.x;
    if (i >= RPBN * NHEADS) return;
    int r = i / NHEADS, h = i % NHEADS;
    t0[h * RPBN + r] = rpb0[i];
    t1[h * RPBN + r] = rpb1[i];
}

// Fused bias gather from transposed tables (L1-resident per-head rows)
__global__ void bias_gather2_kernel(const float* __restrict__ rpbT0,
                                    const float* __restrict__ rpbT1,
                                    const int* __restrict__ rpi,
                                    __half* __restrict__ b0,
                                    __half* __restrict__ b1) {
    int idx = blockIdx.x * blockDim.x + threadIdx.x;
    if (idx >= NHEADS * (BIAS_HN / 2)) return;
    int h  = idx / (BIAS_HN / 2);
    int nm = (idx % (BIAS_HN / 2)) * 2;
    int r0 = rpi[nm], r1 = rpi[nm + 1];
    const float* p0 = rpbT0 + (size_t)h * RPBN;
    const float* p1 = rpbT1 + (size_t)h * RPBN;
    unsigned v0 = pack_h2(p0[r0], p0[r1]);
    unsigned v1 = pack_h2(p1[r0], p1[r1]);
    *(unsigned*)(b0 + (size_t)h * BIAS_HN + nm) = v0;
    *(unsigned*)(b1 + (size_t)h * BIAS_HN + nm) = v1;
}

// ---------------------------------------------------------------------------
// LayerNorm: 4 rows per 256-thread block; 64 threads/row, 12 floats/thread.
// ---------------------------------------------------------------------------
__global__ void __launch_bounds__(256) ln_kernel(const float* __restrict__ in,
                                                 const float* __restrict__ gw,
                                                 const float* __restrict__ gb,
                                                 __half* __restrict__ out,
                                                 const int* __restrict__ map) {
    int rloc = threadIdx.x >> 6;
    int t    = threadIdx.x & 63;
    int r = blockIdx.x * 4 + rloc;
    int src = map ? map[r] : r;
    const float4* xp = (const float4*)(in + (size_t)src * CDIM);
    float4 a = xp[t], b = xp[t + 64], c = xp[t + 128];

    __shared__ float red[4][2];
    __shared__ float stat[4][2];

    float s = (a.x + a.y + a.z + a.w) + (b.x + b.y + b.z + b.w) + (c.x + c.y + c.z + c.w);
    #pragma unroll
    for (int o = 16; o; o >>= 1) s += __shfl_xor_sync(0xffffffffu, s, o);
    if ((t & 31) == 0) red[rloc][t >> 5] = s;
    __syncthreads();
    if (t == 0) stat[rloc][0] = (red[rloc][0] + red[rloc][1]) * (1.0f / CDIM);
    __syncthreads();
    float mu = stat[rloc][0];

    float da[4] = {a.x - mu, a.y - mu, a.z - mu, a.w - mu};
    float db[4] = {b.x - mu, b.y - mu, b.z - mu, b.w - mu};
    float dc[4] = {c.x - mu, c.y - mu, c.z - mu, c.w - mu};
    s = da[0]*da[0] + da[1]*da[1] + da[2]*da[2] + da[3]*da[3]
      + db[0]*db[0] + db[1]*db[1] + db[2]*db[2] + db[3]*db[3]
      + dc[0]*dc[0] + dc[1]*dc[1] + dc[2]*dc[2] + dc[3]*dc[3];
    #pragma unroll
    for (int o = 16; o; o >>= 1) s += __shfl_xor_sync(0xffffffffu, s, o);
    if ((t & 31) == 0) red[rloc][t >> 5] = s;
    __syncthreads();
    if (t == 0) stat[rloc][1] = rsqrtf((red[rloc][0] + red[rloc][1]) * (1.0f / CDIM) + 1e-5f);
    __syncthreads();
    float inv = stat[rloc][1];

    const float4* gwp = (const float4*)gw;
    const float4* gbp = (const float4*)gb;
    __half* o = out + (size_t)r * CDIM;
    #pragma unroll
    for (int seg = 0; seg < 3; seg++) {
        int idx = t + seg * 64;
        float4 g = gwp[idx];
        float4 h = gbp[idx];
        const float* d = seg == 0 ? da : (seg == 1 ? db : dc);
        float v0 = d[0] * inv * g.x + h.x;
        float v1 = d[1] * inv * g.y + h.y;
        float v2 = d[2] * inv * g.z + h.z;
        float v3 = d[3] * inv * g.w + h.w;
        uint2 u;
        u.x = pack_h2(v0, v1);
        u.y = pack_h2(v2, v3);
        *(uint2*)(o + 4 * idx) = u;
    }
}

// ---------------------------------------------------------------------------
// FP16 GEMM: CTA 128x256, BK=64, warp tile 64x64 (2Mx4N), 4-stage cp.async,
// sync->prefetch->wait ordering. SW128 smem, ldmatrix, mma.m16n8k16 fp32 acc.
// ---------------------------------------------------------------------------
#define HASTG 16384
#define HBSTG 32768
#define HGEMM_SMEM (4*HASTG + 4*HBSTG)   // 196608 B

__global__ void __launch_bounds__(256) gemm_h_kernel(
    const __half* __restrict__ A, const __half* __restrict__ W,
    const float* __restrict__ bias, void* __restrict__ Cv,
    int M, int N, int K, int ldC,
    int act_gelu, const int* __restrict__ scatter, int add_resid, int out_half)
{
    extern __shared__ __align__(128) char smg[];
    unsigned sbase = smem_u32(smg);
    unsigned bbase = sbase + 4 * HASTG;
    int tid = threadIdx.x, warp = tid >> 5, lane = tid & 31;
    int wm = warp >> 2, wn = warp & 3;
    int gid = lane >> 2, tig = lane & 3;
    int m0 = blockIdx.y * 128, n0 = blockIdx.x * 256;

    const __half* Ap = A + (size_t)m0 * K;
    const __half* Wp = W + (size_t)n0 * K;
    int NT = K >> 6;

    int ldrow = tid >> 3;
    int ldc   = tid & 7;

    int l7 = lane & 7;
    int a_row = ((lane >> 3) & 1) * 8 + l7;
    int a_cs  = lane >> 4;
    int b_row = ((lane >> 4) & 1) * 8 + l7;
    int b_cs  = (lane >> 3) & 1;

    float acc[4][8][4];
    #pragma unroll
    for (int mi = 0; mi < 4; mi++)
        #pragma unroll
        for (int nj = 0; nj < 8; nj++)
            #pragma unroll
            for (int r = 0; r < 4; r++) acc[mi][nj][r] = 0.0f;

    #pragma unroll
    for (int t = 0; t < 3; t++) {
        #pragma unroll
        for (int l = 0; l < 4; l++) {
            int row = ldrow + l * 32;
            unsigned off = SW128((unsigned)(row * 128 + ldc * 16));
            cp16(sbase + t * HASTG + off, Ap + (size_t)row * K + t * 64 + ldc * 8);
        }
        #pragma unroll
        for (int l = 0; l < 8; l++) {
            int row = ldrow + l * 32;
            unsigned off = SW128((unsigned)(row * 128 + ldc * 16));
            cp16(bbase + t * HBSTG + off, Wp + (size_t)row * K + t * 64 + ldc * 8);
        }
        asm volatile("cp.async.commit_group;" ::: "memory");
    }

    for (int t = 0; t < NT; t++) {
        __syncthreads();
        if (t + 3 < NT) {
            int s2 = (t + 3) & 3;
            #pragma unroll
            for (int l = 0; l < 4; l++) {
                int row = ldrow + l * 32;
                unsigned off = SW128((unsigned)(row * 128 + ldc * 16));
                cp16(sbase + s2 * HASTG + off, Ap + (size_t)row * K + (t+3) * 64 + ldc * 8);
            }
            #pragma unroll
            for (int l = 0; l < 8; l++) {
                int row = ldrow + l * 32;
                unsigned off = SW128((unsigned)(row * 128 + ldc * 16));
                cp16(bbase + s2 * HBSTG + off, Wp + (size_t)row * K + (t+3) * 64 + ldc * 8);
            }
            asm volatile("cp.async.commit_group;" ::: "memory");
            asm volatile("cp.async.wait_group 3;" ::: "memory");
        } else if (t + 3 == NT) {
            asm volatile("cp.async.wait_group 2;" ::: "memory");
        } else if (t + 2 == NT) {
            asm volatile("cp.async.wait_group 1;" ::: "memory");
        } else {
            asm volatile("cp.async.wait_group 0;" ::: "memory");
        }
        __syncthreads();
        unsigned sA = sbase + (t & 3) * HASTG;
        unsigned sB = bbase + (t & 3) * HBSTG;

        #pragma unroll
        for (int s = 0; s < 4; s++) {
            unsigned af[4][4], bf[8][2];
            #pragma unroll
            for (int mi = 0; mi < 4; mi++) {
                int row = wm * 64 + mi * 16 + a_row;
                int ch  = 2 * s + a_cs;
                unsigned ad = sA + SW128((unsigned)(row * 128 + ch * 16));
                LDSM_X4(af[mi][0], af[mi][1], af[mi][2], af[mi][3], ad);
            }
            #pragma unroll
            for (int np = 0; np < 4; np++) {
                int row = wn * 64 + np * 16 + b_row;
                int ch  = 2 * s + b_cs;
                unsigned bd = sB + SW128((unsigned)(row * 128 + ch * 16));
                LDSM_X4(bf[2*np][0], bf[2*np][1], bf[2*np+1][0], bf[2*np+1][1], bd);
            }
            #pragma unroll
            for (int mi = 0; mi < 4; mi++)
                #pragma unroll
                for (int nj = 0; nj < 8; nj++)
                    MMA_F16(acc[mi][nj], af[mi], bf[nj][0], bf[nj][1]);
        }
    }

    float bs0[8], bs1[8];
    #pragma unroll
    for (int nj = 0; nj < 8; nj++) {
        int col = n0 + wn * 64 + nj * 8 + 2 * tig;
        bs0[nj] = bias[col];
        bs1[nj] = bias[col + 1];
    }
    #pragma unroll
    for (int mi = 0; mi < 4; mi++) {
        #pragma unroll
        for (int half = 0; half < 2; half++) {
            int gr = m0 + wm * 64 + mi * 16 + gid + half * 8;
            int tr = scatter ? scatter[gr] : gr;
            #pragma unroll
            for (int nj = 0; nj < 8; nj++) {
                int col = n0 + wn * 64 + nj * 8 + 2 * tig;
                float v0 = acc[mi][nj][half * 2 + 0] + bs0[nj];
                float v1 = acc[mi][nj][half * 2 + 1] + bs1[nj];
                if (act_gelu) { v0 = gelu_f(v0); v1 = gelu_f(v1); }
                if (out_half) {
                    unsigned* hp = (unsigned*)((__half*)Cv + (size_t)tr * ldC + col);
                    *hp = pack_h2(v0, v1);
                } else {
                    float2* cp = (float2*)((float*)Cv + (size_t)tr * ldC + col);
                    if (add_resid) {
                        float2 rv = *cp;
                        v0 += rv.x; v1 += rv.y;
                    }
                    *cp = make_float2(v0, v1);
                }
            }
        }
    }
}

// ---------------------------------------------------------------------------
// Tensor-core window attention, fp16 bias table. 2 CTAs/SM target.
// ---------------------------------------------------------------------------
#define QS_STRIDE 40
#define VT_STRIDE 408
#define ATTN_SMEM_B (400*QS_STRIDE*2*2 + 32*VT_STRIDE*2 + 400*4)

__global__ void __launch_bounds__(256, 2) attn_mma_kernel(
    const __half* __restrict__ qkv,
    const __half* __restrict__ biasT,
    const int* __restrict__ labels,
    __half* __restrict__ out, int shifted)
{
    extern __shared__ __align__(16) char smA[];
    __half* Qs = (__half*)smA;
    __half* Ks = Qs + 400 * QS_STRIDE;
    __half* Vt = Ks + 400 * QS_STRIDE;
    int* lab = (int*)(Vt + 32 * VT_STRIDE);
    int h = blockIdx.x, w = blockIdx.y;
    int tid = threadIdx.x;
    int rbase = w * NTOK;

    const __half hz = __float2half(0.0f);
    for (int i = tid; i < 8 * QS_STRIDE; i += 256) {
        Qs[392 * QS_STRIDE + i] = hz;
        Ks[392 * QS_STRIDE + i] = hz;
    }
    for (int i = tid; i < 32 * 8; i += 256) {
        int d = i >> 3, c = i & 7;
        Vt[d * VT_STRIDE + 392 + c] = hz;
    }

    for (int i = tid; i < 392 * 4; i += 256) {
        int m = i >> 2, c = i & 3;
        const __half* base = qkv + (size_t)(rbase + m) * QKVC + h * HDIM + c * 8;
        *(uint4*)(Qs + m * QS_STRIDE + c * 8) = *(const uint4*)(base);
        *(uint4*)(Ks + m * QS_STRIDE + c * 8) = *(const uint4*)(base + CDIM);
    }
    for (int m = tid; m < 392; m += 256) {
        const uint4* vp = (const uint4*)(qkv + (size_t)(rbase + m) * QKVC + 2 * CDIM + h * HDIM);
        __half vv[32];
        #pragma unroll
        for (int q = 0; q < 4; q++) ((uint4*)vv)[q] = vp[q];
        #pragma unroll
        for (int d = 0; d < 32; d++) Vt[d * VT_STRIDE + m] = vv[d];
    }
    for (int i = tid; i < 400; i += 256)
        lab[i] = (shifted && i < NTOK) ? labels[(w & 7) * NTOK + i] : 0;
    __syncthreads();

    int warp = tid >> 5, lane = tid & 31;
    int gid = lane >> 2, tig = lane & 3;
    int l7 = lane & 7;
    int a_row = ((lane >> 3) & 1) * 8 + l7;
    int a_cs  = lane >> 4;
    int b_row = ((lane >> 4) & 1) * 8 + l7;
    int b_cs  = (lane >> 3) & 1;
    const float scale = 0.17677669529663689f;

    unsigned qsb = smem_u32(Qs);
    unsigned ksb = smem_u32(Ks);
    unsigned vtb = smem_u32(Vt);

    for (int mt = warp; mt < 25; mt += 8) {
        unsigned aq[2][4];
        #pragma unroll
        for (int s = 0; s < 2; s++) {
            unsigned ad = qsb + (unsigned)(((mt * 16 + a_row) * QS_STRIDE + (2*s + a_cs) * 8) * 2);
            LDSM_X4(aq[s][0], aq[s][1], aq[s][2], aq[s][3], ad);
        }
        int q0 = mt * 16 + gid, q1 = q0 + 8;
        int q1ok = (mt != 24);
        int labq0 = lab[q0], labq1 = lab[q1];
        const __half* bp0 = biasT + ((size_t)h * NTOK + q0) * NTOK;
        const __half* bp1 = q1ok ? biasT + ((size_t)h * NTOK + q1) * NTOK : biasT;

        float mr0 = -1e30f, mr1 = -1e30f, lr0 = 0.f, lr1 = 0.f;
        float acc[4][4];
        #pragma unroll
        for (int j = 0; j < 4; j++)
            #pragma unroll
            for (int r = 0; r < 4; r++) acc[j][r] = 0.f;

        for (int nt = 0; nt < 25; nt++) {
            float c0[4] = {0.f, 0.f, 0.f, 0.f};
            float c1[4] = {0.f, 0.f, 0.f, 0.f};
            #pragma unroll
            for (int s = 0; s < 2; s++) {
                unsigned bd = ksb + (unsigned)(((nt * 16 + b_row) * QS_STRIDE + (2*s + b_cs) * 8) * 2);
                unsigned bf0, bf1, bf2, bf3;
                LDSM_X4(bf0, bf1, bf2, bf3, bd);
                MMA_F16(c0, aq[s], bf0, bf1);
                MMA_F16(c1, aq[s], bf2, bf3);
            }
            float sv[2][4];
            #pragma unroll
            for (int f = 0; f < 2; f++) {
                float* c = f ? c1 : c0;
                int k0 = nt * 16 + f * 8 + 2 * tig;
                int kvalid = !(nt == 24 && f == 1);
                if (kvalid) {
                    __half2 hb0 = *(const __half2*)(bp0 + k0);
                    float b00 = __low2float(hb0), b01 = __high2float(hb0);
                    float b10 = 0.f, b11 = 0.f;
                    if (q1ok) {
                        __half2 hb1 = *(const __half2*)(bp1 + k0);
                        b10 = __low2float(hb1); b11 = __high2float(hb1);
                    }
                    float mk0 = 0.f, mk1 = 0.f;
                    if (shifted) {
                        int lk0 = lab[k0], lk1 = lab[k0 + 1];
                        mk0 = (lk0 != labq0) ? -100.f : 0.f;
                        mk1 = (lk1 != labq0) ? -100.f : 0.f;
                        b10 += (lk0 != labq1) ? -100.f : 0.f;
                        b11 += (lk1 != labq1) ? -100.f : 0.f;
                    }
                    sv[f][0] = c[0] * scale + b00 + mk0;
                    sv[f][1] = c[1] * scale + b01 + mk1;
                    sv[f][2] = c[2] * scale + b10;
                    sv[f][3] = c[3] * scale + b11;
                } else {
                    sv[f][0] = sv[f][1] = sv[f][2] = sv[f][3] = -1e30f;
                }
            }
            float tm0 = fmaxf(fmaxf(sv[0][0], sv[0][1]), fmaxf(sv[1][0], sv[1][1]));
            float tm1 = fmaxf(fmaxf(sv[0][2], sv[0][3]), fmaxf(sv[1][2], sv[1][3]));
            tm0 = fmaxf(tm0, __shfl_xor_sync(0xffffffffu, tm0, 1));
            tm0 = fmaxf(tm0, __shfl_xor_sync(0xffffffffu, tm0, 2));
            tm1 = fmaxf(tm1, __shfl_xor_sync(0xffffffffu, tm1, 1));
            tm1 = fmaxf(tm1, __shfl_xor_sync(0xffffffffu, tm1, 2));
            float mn0 = fmaxf(mr0, tm0), mn1 = fmaxf(mr1, tm1);
            float al0 = __expf(mr0 - mn0), al1 = __expf(mr1 - mn1);
            float e[2][4];
            #pragma unroll
            for (int f = 0; f < 2; f++) {
                e[f][0] = __expf(sv[f][0] - mn0);
                e[f][1] = __expf(sv[f][1] - mn0);
                e[f][2] = __expf(sv[f][2] - mn1);
                e[f][3] = __expf(sv[f][3] - mn1);
            }
            float ts0 = e[0][0] + e[0][1] + e[1][0] + e[1][1];
            float ts1 = e[0][2] + e[0][3] + e[1][2] + e[1][3];
            ts0 += __shfl_xor_sync(0xffffffffu, ts0, 1);
            ts0 += __shfl_xor_sync(0xffffffffu, ts0, 2);
            ts1 += __shfl_xor_sync(0xffffffffu, ts1, 1);
            ts1 += __shfl_xor_sync(0xffffffffu, ts1, 2);
            lr0 = lr0 * al0 + ts0;
            lr1 = lr1 * al1 + ts1;
            mr0 = mn0; mr1 = mn1;
            #pragma unroll
            for (int j = 0; j < 4; j++) {
                acc[j][0] *= al0; acc[j][1] *= al0;
                acc[j][2] *= al1; acc[j][3] *= al1;
            }
            unsigned pa[4];
            pa[0] = pack_h2(e[0][0], e[0][1]);
            pa[1] = pack_h2(e[0][2], e[0][3]);
            pa[2] = pack_h2(e[1][0], e[1][1]);
            pa[3] = pack_h2(e[1][2], e[1][3]);
            #pragma unroll
            for (int g = 0; g < 2; g++) {
                unsigned bd = vtb + (unsigned)(((g * 16 + b_row) * VT_STRIDE + nt * 16 + b_cs * 8) * 2);
                unsigned bf0, bf1, bf2, bf3;
                LDSM_X4(bf0, bf1, bf2, bf3, bd);
                MMA_F16(acc[2*g],   pa, bf0, bf1);
                MMA_F16(acc[2*g+1], pa, bf2, bf3);
            }
        }
        float li0 = 1.0f / lr0, li1 = 1.0f / lr1;
        if (q0 < NTOK) {
            __half* op = out + (size_t)(rbase + q0) * CDIM + h * HDIM;
            #pragma unroll
            for (int j = 0; j < 4; j++)
                *(unsigned*)(op + j * 8 + 2 * tig) = pack_h2(acc[j][0] * li0, acc[j][1] * li0);
        }
        if (q1ok) {
            __half* op = out + (size_t)(rbase + q1) * CDIM + h * HDIM;
            #pragma unroll
            for (int j = 0; j < 4; j++)
                *(unsigned*)(op + j * 8 + 2 * tig) = pack_h2(acc[j][2] * li1, acc[j][3] * li1);
        }
    }
}

// ---------------------------------------------------------------------------
// Fused head: c1 (768->64 GEMM + GELU) and c2 (64->2 dot + GELU) in one kernel.
// ---------------------------------------------------------------------------
#define GBM2 64
#define GBK 16
#define A2_STRIDE 68
#define B_STRIDE 68

__global__ void __launch_bounds__(256) head_kernel(
    const __half* __restrict__ A, const float* __restrict__ W,
    const float* __restrict__ bias,
    const float* __restrict__ w2, const float* __restrict__ b2,
    float* __restrict__ out2)
{
    __shared__ float As[GBK * A2_STRIDE];
    __shared__ float Bs[GBK * B_STRIDE];
    __shared__ float Cs[GBM2 * A2_STRIDE];
    __shared__ float w2s[2][64];
    __shared__ float b2s[2];
    int tid = threadIdx.x;
    int tx = tid & 15, ty = tid >> 4;
    int m0 = blockIdx.y * GBM2;
    const __half* Aptr = A + (size_t)m0 * CDIM;
    float acc[4][4];
    #pragma unroll
    for (int i = 0; i < 4; i++)
        #pragma unroll
        for (int j = 0; j < 4; j++) acc[i][j] = 0.0f;

    if (tid < 128) w2s[tid >> 6][tid & 63] = w2[tid];
    if (tid < 2)   b2s[tid] = b2[tid];

    int ldrow = tid >> 2;
    int ldkc  = (tid & 3) * 4;

    for (int k0 = 0; k0 < CDIM; k0 += GBK) {
        {
            const __half* ap = Aptr + (size_t)ldrow * CDIM + k0 + ldkc;
            __half2 h0 = *(const __half2*)(ap);
            __half2 h1 = *(const __half2*)(ap + 2);
            As[(ldkc + 0) * A2_STRIDE + ldrow] = __low2float(h0);
            As[(ldkc + 1) * A2_STRIDE + ldrow] = __high2float(h0);
            As[(ldkc + 2) * A2_STRIDE + ldrow] = __low2float(h1);
            As[(ldkc + 3) * A2_STRIDE + ldrow] = __high2float(h1);
        }
        {
            float4 v = *(const float4*)(W + (size_t)ldrow * CDIM + k0 + ldkc);
            Bs[(ldkc + 0) * B_STRIDE + ldrow] = v.x;
            Bs[(ldkc + 1) * B_STRIDE + ldrow] = v.y;
            Bs[(ldkc + 2) * B_STRIDE + ldrow] = v.z;
            Bs[(ldkc + 3) * B_STRIDE + ldrow] = v.w;
        }
        __syncthreads();
        #pragma unroll
        for (int kk = 0; kk < GBK; kk++) {
            float4 a4 = *(const float4*)&As[kk * A2_STRIDE + ty * 4];
            float4 b4 = *(const float4*)&Bs[kk * B_STRIDE + tx * 4];
            float a[4] = {a4.x, a4.y, a4.z, a4.w};
            float b[4] = {b4.x, b4.y, b4.z, b4.w};
            #pragma unroll
            for (int i = 0; i < 4; i++)
                #pragma unroll
                for (int j = 0; j < 4; j++)
                    acc[i][j] += a[i] * b[j];
        }
        __syncthreads();
    }
    #pragma unroll
    for (int i = 0; i < 4; i++) {
        int row = ty * 4 + i;
        #pragma unroll
        for (int j = 0; j < 4; j++) {
            int col = tx * 4 + j;
            Cs[row * A2_STRIDE + col] = gelu_f(acc[i][j] + bias[col]);
        }
    }
    __syncthreads();
    if (tid < 128) {
        int t = tid >> 1, p = tid & 1;
        const float* row = &Cs[t * A2_STRIDE];
        const float* wp = w2s[p];
        float s = b2s[p];
        #pragma unroll
        for (int k = 0; k < 64; k++) s += row[k] * wp[k];
        out2[(size_t)(m0 + t) * 2 + p] = gelu_f(s);
    }
}

__global__ void final_mul_kernel(const float* __restrict__ o2, float* __restrict__ out) {
    int i = blockIdx.x * blockDim.x + threadIdx.x;
    if (i >= NB * 2 * SPAT) return;
    int b = i / (2 * SPAT);
    int rem = i % (2 * SPAT);
    int p = rem / SPAT;
    int sp = rem % SPAT;
    int t = b * SPAT + sp;
    out[i] = o2[t * 2 + p] * o2[2 * NTOKTOT + t * 2 + p];
}

// ---------------------------------------------------------------------------
extern "C" void kernel_launch(void* const* d_in, const int* in_sizes, int n_in,
                              void* d_out, int out_size) {
    (void)in_sizes; (void)n_in; (void)out_size;
    const float* x      = (const float*)d_in[0];
    const float* n1_g   = (const float*)d_in[1];
    const float* n1_b   = (const float*)d_in[2];
    const float* qkv_w  = (const float*)d_in[3];
    const float* qkv_b  = (const float*)d_in[4];
    const float* proj_w = (const float*)d_in[5];
    const float* proj_b = (const float*)d_in[6];
    const float* rpb    = (const float*)d_in[7];
    const float* n2_g   = (const float*)d_in[8];
    const float* n2_b   = (const float*)d_in[9];
    const float* fc1_w  = (const float*)d_in[10];
    const float* fc1_b  = (const float*)d_in[11];
    const float* fc2_w  = (const float*)d_in[12];
    const float* fc2_b  = (const float*)d_in[13];
    const float* hln_g  = (const float*)d_in[14];
    const float* hln_b  = (const float*)d_in[15];
    const float* c1_w   = (const float*)d_in[16];
    const float* c1_b   = (const float*)d_in[17];
    const float* c2_w   = (const float*)d_in[18];
    const float* c2_b   = (const float*)d_in[19];
    const int*   rpi    = (const int*)d_in[20];
    float* out = (float*)d_out;

    float *xcur0, *out2, *rpbT0;
    __half *bufA0, *bufB0, *qkvh0, *bigh0, *bias0;
    __half *wqkv, *wproj, *wfc1, *wfc2;
    int *map0, *map1, *lab;
    cudaGetSymbolAddress((void**)&xcur0,   g_xcur);
    cudaGetSymbolAddress((void**)&bufA0,   g_bufA);
    cudaGetSymbolAddress((void**)&bufB0,   g_bufB);
    cudaGetSymbolAddress((void**)&qkvh0,   g_qkvh);
    cudaGetSymbolAddress((void**)&bigh0,   g_bigh);
    cudaGetSymbolAddress((void**)&bias0,   g_bias);
    cudaGetSymbolAddress((void**)&rpbT0,   g_rpbT);
    cudaGetSymbolAddress((void**)&out2,    g_out2);
    cudaGetSymbolAddress((void**)&map0,    g_map0);
    cudaGetSymbolAddress((void**)&map1,    g_map1);
    cudaGetSymbolAddress((void**)&lab,     g_lab);
    cudaGetSymbolAddress((void**)&wqkv,    g_wqkv);
    cudaGetSymbolAddress((void**)&wproj,   g_wproj);
    cudaGetSymbolAddress((void**)&wfc1,    g_wfc1);
    cudaGetSymbolAddress((void**)&wfc2,    g_wfc2);

    cudaFuncSetAttribute(attn_mma_kernel, cudaFuncAttributeMaxDynamicSharedMemorySize, ATTN_SMEM_B);
    cudaFuncSetAttribute(gemm_h_kernel, cudaFuncAttributeMaxDynamicSharedMemorySize, HGEMM_SMEM);

    static cudaStream_t s_br1 = nullptr, s_aux[2] = {nullptr, nullptr};
    static cudaEvent_t ev_fork = nullptr, ev_join = nullptr, ev_maps = nullptr, ev_tr = nullptr;
    static cudaEvent_t evA[2], evB[2], evC[2];
    if (s_br1 == nullptr) {
        cudaStreamCreateWithFlags(&s_br1, cudaStreamNonBlocking);
        cudaStreamCreateWithFlags(&s_aux[0], cudaStreamNonBlocking);
        cudaStreamCreateWithFlags(&s_aux[1], cudaStreamNonBlocking);
        cudaEventCreateWithFlags(&ev_fork, cudaEventDisableTiming);
        cudaEventCreateWithFlags(&ev_join, cudaEventDisableTiming);
        cudaEventCreateWithFlags(&ev_maps, cudaEventDisableTiming);
        cudaEventCreateWithFlags(&ev_tr,   cudaEventDisableTiming);
        for (int b = 0; b < 2; b++) {
            cudaEventCreateWithFlags(&evA[b], cudaEventDisableTiming);
            cudaEventCreateWithFlags(&evB[b], cudaEventDisableTiming);
            cudaEventCreateWithFlags(&evC[b], cudaEventDisableTiming);
        }
    }

    cudaEventRecord(ev_fork, 0);
    cudaStreamWaitEvent(s_br1, ev_fork, 0);
    cudaStreamWaitEvent(s_aux[0], ev_fork, 0);
    cudaStreamWaitEvent(s_aux[1], ev_fork, 0);

    build_maps_kernel<<<(NTOKTOT + 255) / 256, 256, 0, s_aux[0]>>>(map0, map1, lab);
    cudaEventRecord(ev_maps, s_aux[0]);
    {
        dim3 blk(32, 8), grd(SPAT / 32, CDIM / 32, NB);
        transpose_dual_kernel<<<grd, blk, 0, 0>>>(x, xcur0, xcur0 + (size_t)NTOKTOT * CDIM);
    }
    cudaEventRecord(ev_tr, 0);
    cudaStreamWaitEvent(0, ev_maps, 0);
    cudaStreamWaitEvent(s_br1, ev_maps, 0);
    cudaStreamWaitEvent(s_br1, ev_tr, 0);

    for (int br = 0; br < 2; br++) {
        cudaStream_t ax = s_aux[br];
        int ib0 = br * 2, ib1 = br * 2 + 1;
        w2h_kernel<<<512, 256, 0, ax>>>(qkv_w + (size_t)br * 2 * QKVC * CDIM,
                                        wqkv + (size_t)br * 2 * QKVC * CDIM, 2 * QKVC * CDIM / 4);
        cudaEventRecord(evA[br], ax);
        rpb_transpose_kernel<<<(RPBN * NHEADS + 255) / 256, 256, 0, ax>>>(
            rpb + (size_t)ib0 * RPBN * NHEADS, rpb + (size_t)ib1 * RPBN * NHEADS,
            rpbT0 + (size_t)ib0 * NHEADS * RPBN, rpbT0 + (size_t)ib1 * NHEADS * RPBN);
        bias_gather2_kernel<<<(NHEADS * (BIAS_HN / 2) + 255) / 256, 256, 0, ax>>>(
            rpbT0 + (size_t)ib0 * NHEADS * RPBN, rpbT0 + (size_t)ib1 * NHEADS * RPBN, rpi,
            bias0 + (size_t)ib0 * NHEADS * BIAS_HN, bias0 + (size_t)ib1 * NHEADS * BIAS_HN);
        cudaEventRecord(evB[br], ax);
        w2h3_kernel<<<1024, 256, 0, ax>>>(
            proj_w + (size_t)br * 2 * CDIM * CDIM, wproj + (size_t)br * 2 * CDIM * CDIM,
            2 * CDIM * CDIM / 4,
            fc1_w + (size_t)br * 2 * MLPC * CDIM,  wfc1 + (size_t)br * 2 * MLPC * CDIM,
            2 * MLPC * CDIM / 4,
            fc2_w + (size_t)br * 2 * CDIM * MLPC,  wfc2 + (size_t)br * 2 * CDIM * MLPC,
            2 * CDIM * MLPC / 4);
        cudaEventRecord(evC[br], ax);
    }

    auto gemm = [&](cudaStream_t st, const __half* A, const __half* W, const float* bias,
                    void* C, int M, int N, int K, int ldC, int gelu, const int* scat,
                    int resid, int out_half) {
        dim3 grid(N / 256, M / 128);
        gemm_h_kernel<<<grid, 256, HGEMM_SMEM, st>>>(A, W, bias, C, M, N, K, ldC,
                                                     gelu, scat, resid, out_half);
    };

    for (int br = 0; br < 2; br++) {
        cudaStream_t st = br ? s_br1 : (cudaStream_t)0;
        float*  xcur  = xcur0  + (size_t)br * NTOKTOT * CDIM;
        __half* bufA  = bufA0  + (size_t)br * NTOKTOT * CDIM;
        __half* bufB  = bufB0  + (size_t)br * NTOKTOT * CDIM;
        __half* qkvh  = qkvh0  + (size_t)br * NTOKTOT * QKVC;
        __half* bigh  = bigh0  + (size_t)br * NTOKTOT * MLPC;

        for (int bl = 0; bl < 2; bl++) {
            int ib = br * 2 + bl;
            int shifted = bl;
            const int* map = shifted ? map1 : map0;
            __half* biasb = bias0 + (size_t)ib * NHEADS * BIAS_HN;

            ln_kernel<<<NTOKTOT / 4, 256, 0, st>>>(xcur, n1_g + ib * CDIM, n1_b + ib * CDIM, bufA, map);

            if (bl == 0) cudaStreamWaitEvent(st, evA[br], 0);
            gemm(st, bufA, wqkv + (size_t)ib * QKVC * CDIM, qkv_b + ib * QKVC,
                 qkvh, NTOKTOT, QKVC, CDIM, QKVC, 0, nullptr, 0, 1);

            if (bl == 0) cudaStreamWaitEvent(st, evB[br], 0);
            {
                dim3 grd(NHEADS, NWIN);
                attn_mma_kernel<<<grd, 256, ATTN_SMEM_B, st>>>(qkvh, biasb, lab, bufB, shifted);
            }

            if (bl == 0) cudaStreamWaitEvent(st, evC[br], 0);
            gemm(st, bufB, wproj + (size_t)ib * CDIM * CDIM, proj_b + ib * CDIM,
                 xcur, NTOKTOT, CDIM, CDIM, CDIM, 0, map, 1, 0);

            ln_kernel<<<NTOKTOT / 4, 256, 0, st>>>(xcur, n2_g + ib * CDIM, n2_b + ib * CDIM, bufA, nullptr);

            gemm(st, bufA, wfc1 + (size_t)ib * MLPC * CDIM, fc1_b + ib * MLPC,
                 bigh, NTOKTOT, MLPC, CDIM, MLPC, 1, nullptr, 0, 1);

            gemm(st, bigh, wfc2 + (size_t)ib * CDIM * MLPC, fc2_b + ib * CDIM,
                 xcur, NTOKTOT, CDIM, MLPC, CDIM, 0, nullptr, 1, 0);
        }
        ln_kernel<<<NTOKTOT / 4, 256, 0, st>>>(xcur, hln_g + br * CDIM, hln_b + br * CDIM, bufA, nullptr);
        {
            dim3 grid(1, NTOKTOT / GBM2);
            head_kernel<<<grid, 256, 0, st>>>(bufA, c1_w + (size_t)br * 64 * CDIM,
                                              c1_b + br * 64, c2_w + br * 2 * 64,
                                              c2_b + br * 2, out2 + (size_t)br * NTOKTOT * 2);
        }
    }

    cudaEventRecord(ev_join, s_br1);
    cudaStreamWaitEvent((cudaStream_t)0, ev_join, 0);
    final_mul_kernel<<<(NB * 2 * SPAT + 255) / 256, 256, 0, 0>>>(out2, out);
}